// round 16
// baseline (speedup 1.0000x reference)
#include <cuda_runtime.h>

// StrictOrthogonal via CholeskyQR1, persistent kernel.
// R16: second grid barrier replaced by a 16-CTA reducer + done-flag:
//   [stage+gram -> partial -> arrive(cnt0)]
//   reducer CTAs (blk<16): spin cnt0==128, reduce slice of S, arrive(cnt1)
//   ALL CTAs: spin cnt1==16 -> [cholinv -> apply -> direct store]
// Avoids the 128-CTA second-arrival skew (the dominant barrier cost).
// 128 CTAs x 512 threads, all co-resident. Deterministic (fixed-order sums).

#define M_ROWS 16384
#define R_COLS 32
#define CHUNK  128
#define NCTA   128
#define TPB    512
#define NRED   16     // reducer CTAs

__device__ float    g_part[2048 * NCTA];   // transposed partials [elem][cta] (1 MB)
__device__ float2   g_S[R_COLS * R_COLS];  // reduced Gram
__device__ unsigned g_cnt[2];              // [0]=arrivals, [1]=reducers done

// ---------------------------------------------------------------------------
// Gram partial: 4 groups of 128 threads, group g covers rows [g*32,g*32+32),
// thread tile 2x4 of the 32x32 output. Groups 1-3 park partials in smem;
// group 0 combines (fixed order) and writes TRANSPOSED to g_part[e][blk].
// ---------------------------------------------------------------------------
__device__ __forceinline__ void gram_phase(const float2* __restrict__ chunk,
                                           float* __restrict__ sc, int blk) {
    const int tid = threadIdx.x;
    const int g  = tid >> 7;        // 0..3
    const int t  = tid & 127;
    const int i0 = (t & 15) * 2;
    const int j0 = (t >> 4) * 4;
    const int r0 = g * 32;

    float2 acc[2][4];
#pragma unroll
    for (int p = 0; p < 2; ++p)
#pragma unroll
        for (int q = 0; q < 4; ++q) acc[p][q] = make_float2(0.f, 0.f);

#pragma unroll 8
    for (int r = 0; r < 32; ++r) {
        const float2* rowc = &chunk[(r0 + r) * R_COLS];
        float4 av  = *reinterpret_cast<const float4*>(rowc + i0);
        float4 bv0 = *reinterpret_cast<const float4*>(rowc + j0);
        float4 bv1 = *reinterpret_cast<const float4*>(rowc + j0 + 2);
        float2 a[2] = { {av.x, av.y}, {av.z, av.w} };
        float2 b[4] = { {bv0.x, bv0.y}, {bv0.z, bv0.w}, {bv1.x, bv1.y}, {bv1.z, bv1.w} };
#pragma unroll
        for (int p = 0; p < 2; ++p)
#pragma unroll
            for (int q = 0; q < 4; ++q) {
                acc[p][q].x = fmaf(a[p].x, b[q].x, acc[p][q].x);
                acc[p][q].x = fmaf(a[p].y, b[q].y, acc[p][q].x);
                acc[p][q].y = fmaf(a[p].x, b[q].y, acc[p][q].y);
                acc[p][q].y = fmaf(-a[p].y, b[q].x, acc[p][q].y);
            }
    }
    __syncthreads();

    if (g != 0) {
#pragma unroll
        for (int p = 0; p < 2; ++p)
#pragma unroll
            for (int q = 0; q < 4; ++q) {
                int e = ((i0 + p) * R_COLS + (j0 + q)) * 2;
                sc[(g - 1) * 2048 + e]     = acc[p][q].x;
                sc[(g - 1) * 2048 + e + 1] = acc[p][q].y;
            }
    }
    __syncthreads();
    if (g == 0) {
#pragma unroll
        for (int p = 0; p < 2; ++p)
#pragma unroll
            for (int q = 0; q < 4; ++q) {
                int e = ((i0 + p) * R_COLS + (j0 + q)) * 2;
                float sx = ((acc[p][q].x + sc[e]) + sc[2048 + e]) + sc[4096 + e];
                float sy = ((acc[p][q].y + sc[e + 1]) + sc[2048 + e + 1]) + sc[4096 + e + 1];
                g_part[(e)     * NCTA + blk] = sx;
                g_part[(e + 1) * NCTA + blk] = sy;
            }
    }
}

// ---------------------------------------------------------------------------
// Warp 0: complex Cholesky of g_S (lane r = row r), L stored transposed in
// smem, diag reciprocals precomputed, k-outer ILP trisolve; W col-major.
// ---------------------------------------------------------------------------
__device__ __forceinline__ void cholinv_phase(float2* __restrict__ LT,
                                              float2* __restrict__ Wcm,
                                              float* __restrict__ sinvd) {
    const unsigned FULL = 0xffffffffu;
    const int r = threadIdx.x;

    float2 row[R_COLS];
#pragma unroll
    for (int c = 0; c < R_COLS; ++c) row[c] = __ldcg(&g_S[r * R_COLS + c]);

#pragma unroll
    for (int k = 0; k < R_COLS; ++k) {
        float dkk  = __shfl_sync(FULL, row[k].x, k);
        float invs = rsqrtf(dkk);
        float2 lv;
        lv.x = row[k].x * invs;
        lv.y = row[k].y * invs;
        row[k] = lv;
#pragma unroll
        for (int j = k + 1; j < R_COLS; ++j) {
            float lx = __shfl_sync(FULL, lv.x, j);
            float ly = __shfl_sync(FULL, lv.y, j);
            row[j].x -= lv.x * lx + lv.y * ly;
            row[j].y -= lv.y * lx - lv.x * ly;
        }
    }

#pragma unroll
    for (int k = 0; k < R_COLS; ++k)
        if (k <= r) LT[k * R_COLS + r] = row[k];
    __syncwarp();
    sinvd[r] = 1.0f / LT[r * R_COLS + r].x;
    __syncwarp();

    float2 s[R_COLS];
#pragma unroll
    for (int j = 0; j < R_COLS; ++j)
        s[j] = (j == r) ? make_float2(1.f, 0.f) : make_float2(0.f, 0.f);

#pragma unroll
    for (int k = 0; k < R_COLS; ++k) {
        float dk = sinvd[k];
        s[k].x *= dk;
        s[k].y *= dk;
#pragma unroll
        for (int j = k + 1; j < R_COLS; ++j) {
            float2 lv = LT[k * R_COLS + j];
            s[j].x -= lv.x * s[k].x - lv.y * s[k].y;
            s[j].y -= lv.x * s[k].y + lv.y * s[k].x;
        }
    }

    // W[c][j] = conj(x[j]) -> col-major Wcm[j*32 + c]; exact 0 for j < c.
#pragma unroll
    for (int j = 0; j < R_COLS; ++j)
        Wcm[j * R_COLS + r] = make_float2(s[j].x, -s[j].y);
}

// ---------------------------------------------------------------------------
__global__ __launch_bounds__(TPB, 1) void fused_cholqr1(const float2* __restrict__ A,
                                                        float2* __restrict__ Out) {
    __shared__ float2 chunk[CHUNK * R_COLS];   // 32 KB resident rows
    __shared__ float  sc[3 * 2048];            // 24 KB gram bufs / LT / Wcm
    __shared__ float  sinvd[R_COLS];

    const int tid = threadIdx.x;
    const int blk = blockIdx.x;

    // Stage chunk (only read of A): 2048 float4 over 512 threads.
    {
        const float4* src = reinterpret_cast<const float4*>(A + (size_t)blk * CHUNK * R_COLS);
        float4* dst = reinterpret_cast<float4*>(chunk);
#pragma unroll
        for (int i = 0; i < 4; ++i) dst[tid + TPB * i] = src[tid + TPB * i];
    }
    __syncthreads();

    gram_phase(chunk, sc, blk);

    // ---- arrive: partial published ----
    __syncthreads();
    if (tid == 0) {
        __threadfence();
        atomicAdd(&g_cnt[0], 1u);
    }

    // ---- reducer CTAs: wait for all partials, reduce slice of S ----
    if (blk < NRED) {
        if (tid == 0) {
            volatile unsigned* p = &g_cnt[0];
            while (*p < NCTA) __nanosleep(16);
            __threadfence();
        }
        __syncthreads();

        // This CTA reduces elements [blk*128, blk*128+128): 16 warps x 8 elems.
        const int w = tid >> 5;
        const int l = tid & 31;
#pragma unroll
        for (int i = 0; i < 8; ++i) {
            const int e = blk * 128 + w * 8 + i;
            float4 v = __ldcg(reinterpret_cast<const float4*>(&g_part[(size_t)e * NCTA]) + l);
            float s = (v.x + v.y) + (v.z + v.w);
            s += __shfl_down_sync(0xffffffffu, s, 16);
            s += __shfl_down_sync(0xffffffffu, s, 8);
            s += __shfl_down_sync(0xffffffffu, s, 4);
            s += __shfl_down_sync(0xffffffffu, s, 2);
            s += __shfl_down_sync(0xffffffffu, s, 1);
            if (l == 0) reinterpret_cast<float*>(g_S)[e] = s;
        }
        __syncthreads();
        if (tid == 0) {
            __threadfence();
            atomicAdd(&g_cnt[1], 1u);
        }
    }

    // ---- everyone: wait for S complete (16 reducer flags) ----
    if (tid == 0) {
        volatile unsigned* p = &g_cnt[1];
        while (*p < NRED) __nanosleep(16);
        __threadfence();
    }
    __syncthreads();

    // ---- cholinv (warp 0), then apply + direct store ----
    float2* LT  = reinterpret_cast<float2*>(sc);          // 8 KB
    float2* Wcm = reinterpret_cast<float2*>(sc + 2048);   // 8 KB

    if (tid < 32) cholinv_phase(LT, Wcm, sinvd);
    __syncthreads();                // Wcm ready

    const int row = tid >> 2;       // 0..127
    const int c0  = tid & 3;

    float2 a[R_COLS];
    {
        const float4* rp = reinterpret_cast<const float4*>(&chunk[row * R_COLS]);
#pragma unroll
        for (int i = 0; i < 16; ++i) {
            float4 v = rp[i];
            a[2 * i]     = make_float2(v.x, v.y);
            a[2 * i + 1] = make_float2(v.z, v.w);
        }
    }

    float2* outr = Out + ((size_t)blk * CHUNK + row) * R_COLS;
#pragma unroll
    for (int jj = 0; jj < 8; ++jj) {
        const int j = 4 * jj + c0;
        const float2* wj = &Wcm[j * R_COLS];
        float2 s = make_float2(0.f, 0.f);
#pragma unroll
        for (int i = 0; i < R_COLS; ++i) {
            if (i <= 4 * jj + 3) {          // compile-time prune of tail
                if (i <= j) {               // runtime triangular guard
                    float2 w = wj[i];
                    s.x = fmaf(a[i].x, w.x, s.x);
                    s.x = fmaf(-a[i].y, w.y, s.x);
                    s.y = fmaf(a[i].x, w.y, s.y);
                    s.y = fmaf(a[i].y, w.x, s.y);
                }
            }
        }
        outr[j] = s;                        // direct global store
    }
}

// ---------------------------------------------------------------------------
extern "C" void kernel_launch(void* const* d_in, const int* in_sizes, int n_in,
                              void* d_out, int out_size) {
    (void)in_sizes; (void)n_in; (void)out_size;
    const float2* A = reinterpret_cast<const float2*>(d_in[0]);
    float2* Out = reinterpret_cast<float2*>(d_out);

    void* cp = nullptr;
    cudaGetSymbolAddress(&cp, g_cnt);
    cudaMemsetAsync(cp, 0, sizeof(unsigned) * 2);   // measured ~free (R15)

    fused_cholqr1<<<NCTA, TPB>>>(A, Out);
}